// round 5
// baseline (speedup 1.0000x reference)
#include <cuda_runtime.h>
#include <math.h>

#define NV 512
#define DIM 256
#define HD 64
#define EPSLN 1e-5f

struct Scratch {
    float Wh1[NV*DIM], Aa[NV*DIM], Bb[NV*DIM];
    float adjf[NV*NV];
    float Xt[NV*2*DIM];
    float thp0[NV*DIM], thp1[NV*DIM];
    float chp0[NV*DIM], chp1[NV*DIM], chp2[NV*DIM];
    float tf[NV*HD];
    float E[NV], U[NV*DIM], D[NV];
    float Np0[NV*DIM], Np1[NV*DIM], Np2[NV*DIM], Np3[NV*DIM];
    float wc[DIM];
    float Sp0[NV*NV], Sp1[NV*NV];
    float mb[64], seb[64], gpart[64*DIM];
    float H2[HD], H3[NV*HD];
    float ci[NV*3*DIM], cf4[NV*HD], h4[HD];
    float Hcp0[NV*DIM], Hcp1[NV*DIM];
    float op[NV*DIM];
};
__device__ Scratch g_s;

__device__ __forceinline__ float ninf() { return __int_as_float(0xff800000); }

// ---------- loaders ----------
struct LdA {
    const float* A; int ld;
    __device__ __forceinline__ float operator()(int i, int k) const { return A[i*ld + k]; }
};
struct LdRelu2 {
    const float *p0, *p1, *b;
    __device__ __forceinline__ float operator()(int i, int k) const {
        return fmaxf(p0[i*DIM+k] + p1[i*DIM+k] + b[k], 0.f);
    }
};
struct LdRelu3 {
    const float *p0, *p1, *p2, *b;
    __device__ __forceinline__ float operator()(int i, int k) const {
        return fmaxf(p0[i*DIM+k] + p1[i*DIM+k] + p2[i*DIM+k] + b[k], 0.f);
    }
};
struct LdSum2 {
    const float *p0, *p1;
    __device__ __forceinline__ float operator()(int i, int k) const {
        return p0[i*DIM+k] + p1[i*DIM+k];
    }
};
struct LdHcat {
    const float *n0, *n1, *n2, *n3, *Dv, *H2, *H3, *h4;
    __device__ __forceinline__ float operator()(int i, int c) const {
        if (c < 256) return (n0[i*DIM+c] + n1[i*DIM+c] + n2[i*DIM+c] + n3[i*DIM+c]) / Dv[i];
        if (c < 320) return H2[c - 256];
        if (c < 384) return H3[i*HD + (c - 320)];
        return (i < HD) ? h4[i] : 0.f;
    }
};

// ---------- 64x64 GEMM tile over k range [kbeg,kend) ----------
template <class FA>
__device__ __forceinline__ void gemm_core(const FA& loadA, const float* __restrict__ W,
                                          const float* __restrict__ bias, float* __restrict__ C,
                                          int Nn, int kbeg, int kend, int relu,
                                          int bi, int bj, float* buf) {
    float (*sA)[68] = (float(*)[68])buf;
    float (*sW)[68] = (float(*)[68])(buf + 16*68);
    int tid = threadIdx.x, tx = tid & 15, ty = tid >> 4;
    float acc[4][4];
#pragma unroll
    for (int r = 0; r < 4; r++)
#pragma unroll
        for (int c = 0; c < 4; c++) acc[r][c] = 0.f;

    for (int k0 = kbeg; k0 < kend; k0 += 16) {
#pragma unroll
        for (int p = 0; p < 4; p++) {
            int t = tid + p * 256;
            int ia = t >> 4, ka = t & 15, kk = k0 + ka;
            sA[ka][ia] = (kk < kend) ? loadA(bi + ia, kk) : 0.f;
            int kw = t >> 6, jw = t & 63, k2 = k0 + kw;
            sW[kw][jw] = (k2 < kend) ? W[k2 * Nn + bj + jw] : 0.f;
        }
        __syncthreads();
#pragma unroll
        for (int k = 0; k < 16; k++) {
            float4 av = *(const float4*)&sA[k][ty*4];
            float4 wv = *(const float4*)&sW[k][tx*4];
            acc[0][0] += av.x*wv.x; acc[0][1] += av.x*wv.y; acc[0][2] += av.x*wv.z; acc[0][3] += av.x*wv.w;
            acc[1][0] += av.y*wv.x; acc[1][1] += av.y*wv.y; acc[1][2] += av.y*wv.z; acc[1][3] += av.y*wv.w;
            acc[2][0] += av.z*wv.x; acc[2][1] += av.z*wv.y; acc[2][2] += av.z*wv.z; acc[2][3] += av.z*wv.w;
            acc[3][0] += av.w*wv.x; acc[3][1] += av.w*wv.y; acc[3][2] += av.w*wv.z; acc[3][3] += av.w*wv.w;
        }
        __syncthreads();
    }
#pragma unroll
    for (int r = 0; r < 4; r++) {
        int i = bi + ty*4 + r;
#pragma unroll
        for (int c = 0; c < 4; c++) {
            int j = bj + tx*4 + c;
            float v = acc[r][c];
            if (bias) v += bias[j];
            if (relu) v = fmaxf(v, 0.f);
            C[i * Nn + j] = v;
        }
    }
}

// ---------- Wave 0: adjf, Xt, ci(neighbors), wc ----------
struct W0P {
    const int* adj; const float* V; const float* ph;
    const float* cew2; const float* ac0; const float* ac1;
    float* adjf; float* Xt; float* ci; float* wc;
};
__global__ void k_w0(W0P p) {
    int bid = blockIdx.x, tid = threadIdx.x;
    if (bid < 256) {
        int idx = bid * 256 + tid;
        for (int t = idx; t < NV*NV; t += 65536) p.adjf[t] = (float)p.adj[t];
        for (int t = idx; t < NV*2*DIM; t += 65536) {
            int i = t >> 9, c = t & 511;
            p.Xt[t] = (c < DIM) ? p.V[i*DIM + c] : p.ph[i*DIM + (c - DIM)];
        }
    } else if (bid < 320) {
        int i = (bid - 256) * 8 + (tid >> 5);
        int lane = tid & 31;
        int found = 0, n0 = 0, n1 = 0;
        for (int base = 0; base < NV && found < 2; base += 32) {
            int a = p.adj[i*NV + base + lane];
            unsigned m = __ballot_sync(0xffffffffu, a == 1);
            while (m && found < 2) {
                int b = __ffs(m) - 1;
                if (found == 0) n0 = base + b; else n1 = base + b;
                found++;
                m &= m - 1;
            }
        }
        int valid = (found == 2);
        for (int c = lane; c < DIM; c += 32) {
            p.ci[i*(3*DIM) + c]         = p.V[i*DIM + c];
            p.ci[i*(3*DIM) + DIM + c]   = valid ? p.V[n0*DIM + c] : 0.f;
            p.ci[i*(3*DIM) + 2*DIM + c] = valid ? p.V[n1*DIM + c] : 0.f;
        }
    } else {
        __shared__ float a[HD];
        if (tid < HD) a[tid] = p.ac0[tid] + p.ac1[tid];
        __syncthreads();
        float s = 0.f;
        for (int d = 0; d < HD; d++) s += p.cew2[tid*HD + d] * a[d];
        p.wc[tid] = s;
    }
}

// ---------- Wave 1: big input GEMMs, K-split, 256 CTAs ----------
struct W1P {
    const float *V, *W1, *cew1, *ceb1, *Xt, *tew1, *ci, *cow1;
    float *Wh1, *Aa, *Bb, *thp0, *thp1, *chp0, *chp1, *chp2;
};
__global__ void k_w1(W1P p) {
    __shared__ __align__(16) float buf[2*16*68];
    int b = blockIdx.x;
    if (b < 32) {
        gemm_core(LdA{p.V, DIM}, p.W1, nullptr, p.Wh1, DIM, 0, DIM, 0, (b>>2)*64, (b&3)*64, buf);
    } else if (b < 64) {
        int q = b - 32;
        gemm_core(LdA{p.V, DIM}, p.cew1, p.ceb1, p.Aa, DIM, 0, DIM, 0, (q>>2)*64, (q&3)*64, buf);
    } else if (b < 96) {
        int q = b - 64;
        gemm_core(LdA{p.V, DIM}, p.cew1 + DIM*DIM, nullptr, p.Bb, DIM, 0, DIM, 0, (q>>2)*64, (q&3)*64, buf);
    } else if (b < 160) {
        int q = b - 96, half = q >> 5, t = q & 31;
        float* out = half ? p.thp1 : p.thp0;
        gemm_core(LdA{p.Xt, 2*DIM}, p.tew1, nullptr, out, DIM, half*256, half*256+256, 0,
                  (t>>2)*64, (t&3)*64, buf);
    } else {
        int q = b - 160, third = q >> 5, t = q & 31;
        float* out = (third == 0) ? p.chp0 : (third == 1) ? p.chp1 : p.chp2;
        gemm_core(LdA{p.ci, 3*DIM}, p.cow1, nullptr, out, DIM, third*256, third*256+256, 0,
                  (t>>2)*64, (t&3)*64, buf);
    }
}

// ---------- Wave 2: pair pass1 (k-split) + tf + cf4 + vecE, 208 CTAs ----------
struct W2P {
    const float *Aa, *Bb, *wc;
    const float *thp0, *thp1, *teb1, *tew2, *teb2;
    const float *chp0, *chp1, *chp2, *cob1, *cow2, *cob2;
    const float *Wh1, *astd1;
    float *Sp0, *Sp1, *tf, *cf4, *E, *U;
};
__global__ void k_w2(W2P p) {
    __shared__ __align__(16) float buf[2*32*68 + 64];
    int bid = blockIdx.x, tid = threadIdx.x;
    if (bid < 128) {
        // pair pass1: partial scores over half the K range
        float (*sA)[68] = (float(*)[68])buf;
        float (*sB)[68] = (float(*)[68])(buf + 32*68);
        float* swc = buf + 64*68;
        int b = bid >> 1, h = bid & 1;
        int bi = (b >> 3) * 64, bj = (b & 7) * 64;
        int kbeg = h * 128;
        int tx = tid & 15, ty = tid >> 4;
        float acc[4][4];
#pragma unroll
        for (int r = 0; r < 4; r++)
#pragma unroll
            for (int c = 0; c < 4; c++) acc[r][c] = 0.f;

        for (int k0 = kbeg; k0 < kbeg + 128; k0 += 32) {
#pragma unroll
            for (int q = 0; q < 8; q++) {
                int t = tid + q * 256;
                int i = t >> 5, k = t & 31;
                sA[k][i] = p.Aa[(bi + i) * DIM + k0 + k];
                sB[k][i] = p.Bb[(bj + i) * DIM + k0 + k];
            }
            if (tid < 32) swc[tid] = p.wc[k0 + tid];
            __syncthreads();
#pragma unroll
            for (int k = 0; k < 32; k++) {
                float wk = swc[k];
                float4 av = *(const float4*)&sA[k][ty*4];
                float4 bv = *(const float4*)&sB[k][tx*4];
                acc[0][0] += fmaxf(av.x+bv.x,0.f)*wk; acc[0][1] += fmaxf(av.x+bv.y,0.f)*wk;
                acc[0][2] += fmaxf(av.x+bv.z,0.f)*wk; acc[0][3] += fmaxf(av.x+bv.w,0.f)*wk;
                acc[1][0] += fmaxf(av.y+bv.x,0.f)*wk; acc[1][1] += fmaxf(av.y+bv.y,0.f)*wk;
                acc[1][2] += fmaxf(av.y+bv.z,0.f)*wk; acc[1][3] += fmaxf(av.y+bv.w,0.f)*wk;
                acc[2][0] += fmaxf(av.z+bv.x,0.f)*wk; acc[2][1] += fmaxf(av.z+bv.y,0.f)*wk;
                acc[2][2] += fmaxf(av.z+bv.z,0.f)*wk; acc[2][3] += fmaxf(av.z+bv.w,0.f)*wk;
                acc[3][0] += fmaxf(av.w+bv.x,0.f)*wk; acc[3][1] += fmaxf(av.w+bv.y,0.f)*wk;
                acc[3][2] += fmaxf(av.w+bv.z,0.f)*wk; acc[3][3] += fmaxf(av.w+bv.w,0.f)*wk;
            }
            __syncthreads();
        }
        float* Sp = h ? p.Sp1 : p.Sp0;
#pragma unroll
        for (int r = 0; r < 4; r++)
#pragma unroll
            for (int c = 0; c < 4; c++)
                Sp[(bi + ty*4 + r) * NV + bj + tx*4 + c] = acc[r][c];
    } else if (bid < 136) {
        gemm_core(LdRelu2{p.thp0, p.thp1, p.teb1}, p.tew2, p.teb2, p.tf, HD,
                  0, DIM, 0, (bid - 128) * 64, 0, buf);
    } else if (bid < 144) {
        gemm_core(LdRelu3{p.chp0, p.chp1, p.chp2, p.cob1}, p.cow2, p.cob2, p.cf4, HD,
                  0, DIM, 0, (bid - 136) * 64, 0, buf);
    } else {
        int w = (bid - 144) * 8 + (tid >> 5);
        int lane = tid & 31;
        float pr = 0.f;
        for (int k = lane; k < DIM; k += 32) pr += p.Wh1[w*DIM + k] * p.astd1[k];
#pragma unroll
        for (int o = 16; o; o >>= 1) pr += __shfl_xor_sync(0xffffffffu, pr, o);
        float ev = expf(pr);
        if (lane == 0) p.E[w] = ev;
        for (int k = lane; k < DIM; k += 32) p.U[w*DIM + k] = ev * p.Wh1[w*DIM + k];
    }
}

// ---------- Wave 3: pair pass2 + Num(split4) + vecD + H3 + h4, 323 CTAs ----------
struct W3P {
    const float *Aa, *Bb, *Sp0, *Sp1;
    const float *adjf, *U, *E, *tf, *cf4;
    float *mb, *seb, *gpart, *Np0, *Np1, *Np2, *Np3, *D, *H3, *h4;
};
__global__ void k_w3(W3P p) {
    __shared__ __align__(16) float buf[2*32*68 + 256 + 1024 + 64];
    int bid = blockIdx.x, tid = threadIdx.x;
    if (bid < 128) {
        // pair pass2
        float (*sA)[68] = (float(*)[68])buf;
        float (*sB)[68] = (float(*)[68])(buf + 32*68);
        float* red = buf + 64*68;
        float* gsh = red + 256;
        int b = bid >> 1, h = bid & 1;
        int bi = (b >> 3) * 64, bj = (b & 7) * 64;
        int kbeg = h * 128;
        int tx = tid & 15, ty = tid >> 4;
        int warp = tid >> 5, lane = tid & 31;

        float e[4][4];
        float m = ninf();
#pragma unroll
        for (int r = 0; r < 4; r++)
#pragma unroll
            for (int c = 0; c < 4; c++) {
                int i = bi + ty*4 + r, j = bj + tx*4 + c;
                float sv = p.Sp0[i*NV + j] + p.Sp1[i*NV + j];
                if (i == j) sv = ninf();
                e[r][c] = sv;
                m = fmaxf(m, sv);
            }
        red[tid] = m; __syncthreads();
        for (int o = 128; o; o >>= 1) { if (tid < o) red[tid] = fmaxf(red[tid], red[tid+o]); __syncthreads(); }
        float M = red[0];
        __syncthreads();
        float se = 0.f;
#pragma unroll
        for (int r = 0; r < 4; r++)
#pragma unroll
            for (int c = 0; c < 4; c++) { float ev = expf(e[r][c] - M); e[r][c] = ev; se += ev; }
        red[tid] = se; __syncthreads();
        for (int o = 128; o; o >>= 1) { if (tid < o) red[tid] += red[tid+o]; __syncthreads(); }
        if (h == 0 && tid == 0) { p.mb[b] = M; p.seb[b] = red[0]; }

        for (int k0 = kbeg; k0 < kbeg + 128; k0 += 32) {
#pragma unroll
            for (int q = 0; q < 8; q++) {
                int t = tid + q * 256;
                int i = t >> 5, k = t & 31;
                sA[k][i] = p.Aa[(bi + i) * DIM + k0 + k];
                sB[k][i] = p.Bb[(bj + i) * DIM + k0 + k];
            }
            __syncthreads();
#pragma unroll
            for (int k = 0; k < 32; k++) {
                float4 av = *(const float4*)&sA[k][ty*4];
                float4 bv = *(const float4*)&sB[k][tx*4];
                float pk = 0.f;
                pk += e[0][0]*fmaxf(av.x+bv.x,0.f); pk += e[0][1]*fmaxf(av.x+bv.y,0.f);
                pk += e[0][2]*fmaxf(av.x+bv.z,0.f); pk += e[0][3]*fmaxf(av.x+bv.w,0.f);
                pk += e[1][0]*fmaxf(av.y+bv.x,0.f); pk += e[1][1]*fmaxf(av.y+bv.y,0.f);
                pk += e[1][2]*fmaxf(av.y+bv.z,0.f); pk += e[1][3]*fmaxf(av.y+bv.w,0.f);
                pk += e[2][0]*fmaxf(av.z+bv.x,0.f); pk += e[2][1]*fmaxf(av.z+bv.y,0.f);
                pk += e[2][2]*fmaxf(av.z+bv.z,0.f); pk += e[2][3]*fmaxf(av.z+bv.w,0.f);
                pk += e[3][0]*fmaxf(av.w+bv.x,0.f); pk += e[3][1]*fmaxf(av.w+bv.y,0.f);
                pk += e[3][2]*fmaxf(av.w+bv.z,0.f); pk += e[3][3]*fmaxf(av.w+bv.w,0.f);
#pragma unroll
                for (int o = 16; o; o >>= 1) pk += __shfl_down_sync(0xffffffffu, pk, o);
                if (lane == 0) gsh[(k0 - kbeg + k) * 8 + warp] = pk;
            }
            __syncthreads();
        }
        if (tid < 128) {
            float s8 = 0.f;
#pragma unroll
            for (int w2 = 0; w2 < 8; w2++) s8 += gsh[tid * 8 + w2];
            p.gpart[b * DIM + kbeg + tid] = s8;
        }
    } else if (bid < 256) {
        int q = bid - 128, ks = q >> 5, t = q & 31;
        float* out = (ks == 0) ? p.Np0 : (ks == 1) ? p.Np1 : (ks == 2) ? p.Np2 : p.Np3;
        gemm_core(LdA{p.adjf, NV}, p.U, nullptr, out, DIM, ks*128, ks*128+128, 0,
                  (t>>2)*64, (t&3)*64, buf);
    } else if (bid < 320) {
        int w = (bid - 256) * 8 + (tid >> 5);
        int lane = tid & 31;
        float pr = 0.f;
        for (int j = lane; j < NV; j += 32) pr += p.adjf[w*NV + j] * p.E[j];
#pragma unroll
        for (int o = 16; o; o >>= 1) pr += __shfl_xor_sync(0xffffffffu, pr, o);
        if (lane == 0) p.D[w] = pr;
    } else if (bid == 320) {
        // H3: 16-chunk scan of tf
        float* cs = buf;  // 16*64
        int d = tid & 63, g = tid >> 6;  // g in 0..3
        float s0 = 0.f, s1 = 0.f, s2 = 0.f, s3 = 0.f;
        for (int r = 0; r < 32; r++) {
            s0 += p.tf[(32*(4*g+0)+r)*HD + d];
            s1 += p.tf[(32*(4*g+1)+r)*HD + d];
            s2 += p.tf[(32*(4*g+2)+r)*HD + d];
            s3 += p.tf[(32*(4*g+3)+r)*HD + d];
        }
        cs[(4*g+0)*64 + d] = s0; cs[(4*g+1)*64 + d] = s1;
        cs[(4*g+2)*64 + d] = s2; cs[(4*g+3)*64 + d] = s3;
        __syncthreads();
#pragma unroll
        for (int cc = 0; cc < 4; cc++) {
            int c = 4*g + cc;
            float pre = 0.f;
            for (int c2 = 0; c2 < c; c2++) pre += cs[c2*64 + d];
            float run = pre;
            for (int r = 0; r < 32; r++) {
                int row = 32*c + r;
                run += p.tf[row*HD + d];
                p.H3[row*HD + d] = run / (float)(row + 1);
            }
        }
    } else {
        // h4 = column sums of cf4
        int d = tid & 63, g = tid >> 6;
        float s = 0.f;
        for (int r = g; r < NV; r += 4) s += p.cf4[r*HD + d];
        buf[tid] = s; __syncthreads();
        if (tid < 64) p.h4[tid] = buf[tid] + buf[tid+64] + buf[tid+128] + buf[tid+192];
    }
}

// ---------- H2 combiner ----------
__global__ void k_h2c(const float* __restrict__ mb, const float* __restrict__ seb,
                      const float* __restrict__ gpart, const float* __restrict__ cew2,
                      const float* __restrict__ ceb2, float* __restrict__ H2) {
    __shared__ float sw[64];
    __shared__ float ga[DIM];
    __shared__ float Msh, invSh;
    int tid = threadIdx.x;
    if (tid == 0) {
        float M = ninf();
        for (int b = 0; b < 64; b++) M = fmaxf(M, mb[b]);
        Msh = M;
    }
    __syncthreads();
    if (tid < 64) sw[tid] = expf(mb[tid] - Msh);
    __syncthreads();
    if (tid == 0) {
        float s = 0.f;
        for (int b = 0; b < 64; b++) s += seb[b] * sw[b];
        invSh = 1.f / s;
    }
    __syncthreads();
    float g = 0.f;
    for (int b = 0; b < 64; b++) g += gpart[b * DIM + tid] * sw[b];
    ga[tid] = g * invSh;
    __syncthreads();
    if (tid < 64) {
        float s = 0.f;
        for (int k = 0; k < DIM; k++) s += ga[k] * cew2[k*HD + tid];
        H2[tid] = s + ceb2[tid];
    }
}

// ---------- Wave 5: Hc = Hcat@W2 (on-the-fly Hcat, K split 2) ----------
struct W5P {
    const float *Np0, *Np1, *Np2, *Np3, *D, *H2, *H3, *h4, *W2;
    float *Hcp0, *Hcp1;
};
__global__ void k_w5(W5P p) {
    __shared__ __align__(16) float buf[2*16*68];
    int b = blockIdx.x;
    int ks = b >> 5, t = b & 31;
    int kbeg = ks ? 208 : 0, kend = ks ? 385 : 208;
    float* out = ks ? p.Hcp1 : p.Hcp0;
    LdHcat ld{p.Np0, p.Np1, p.Np2, p.Np3, p.D, p.H2, p.H3, p.h4};
    gemm_core(ld, p.W2, nullptr, out, DIM, kbeg, kend, 0, (t>>2)*64, (t&3)*64, buf);
}

// ---------- Wave 6: op = (Hcp0+Hcp1)@Wo + bo ----------
__global__ void k_w6(const float* Hcp0, const float* Hcp1, const float* Wo,
                     const float* bo, float* op) {
    __shared__ __align__(16) float buf[2*16*68];
    int b = blockIdx.x;
    gemm_core(LdSum2{Hcp0, Hcp1}, Wo, bo, op, DIM, 0, DIM, 0, (b>>2)*64, (b&3)*64, buf);
}

// ---------- layernorm + elu ----------
__global__ void k_lnelu(const float* __restrict__ op, const float* __restrict__ g,
                        const float* __restrict__ b, float* __restrict__ out) {
    __shared__ float red[256];
    __shared__ float smu, svar;
    int i = blockIdx.x, t = threadIdx.x;
    float x = op[i*DIM + t];
    red[t] = x; __syncthreads();
    for (int o = 128; o; o >>= 1) { if (t < o) red[t] += red[t+o]; __syncthreads(); }
    if (t == 0) smu = red[0] / (float)DIM;
    __syncthreads();
    float d = x - smu;
    red[t] = d * d; __syncthreads();
    for (int o = 128; o; o >>= 1) { if (t < o) red[t] += red[t+o]; __syncthreads(); }
    if (t == 0) svar = red[0] / (float)DIM;
    __syncthreads();
    float y = d * rsqrtf(svar + EPSLN) * g[t] + b[t];
    out[i*DIM + t] = (y > 0.f) ? y : expm1f(y);
}

extern "C" void kernel_launch(void* const* d_in, const int* in_sizes, int n_in,
                              void* d_out, int out_size) {
    const float* V      = (const float*)d_in[0];
    const int*   adj    = (const int*)d_in[1];
    const float* ph     = (const float*)d_in[2];
    const float* W1     = (const float*)d_in[3];
    const float* a_std1 = (const float*)d_in[5];
    const float* ce_w1  = (const float*)d_in[6];
    const float* ce_b1  = (const float*)d_in[7];
    const float* ce_w2  = (const float*)d_in[8];
    const float* ce_b2  = (const float*)d_in[9];
    const float* a_c0   = (const float*)d_in[10];
    const float* a_c1   = (const float*)d_in[11];
    const float* te_w1  = (const float*)d_in[12];
    const float* te_b1  = (const float*)d_in[13];
    const float* te_w2  = (const float*)d_in[14];
    const float* te_b2  = (const float*)d_in[15];
    const float* co_w1  = (const float*)d_in[18];
    const float* co_b1  = (const float*)d_in[19];
    const float* co_w2  = (const float*)d_in[20];
    const float* co_b2  = (const float*)d_in[21];
    const float* W2     = (const float*)d_in[24];
    const float* Wo     = (const float*)d_in[25];
    const float* bo     = (const float*)d_in[26];
    const float* ln_g   = (const float*)d_in[27];
    const float* ln_b   = (const float*)d_in[28];
    float* out = (float*)d_out;

    Scratch* s = nullptr;
    cudaGetSymbolAddress((void**)&s, g_s);

    W0P p0 = { adj, V, ph, ce_w2, a_c0, a_c1, s->adjf, s->Xt, s->ci, s->wc };
    k_w0<<<321, 256>>>(p0);

    W1P p1 = { V, W1, ce_w1, ce_b1, s->Xt, te_w1, s->ci, co_w1,
               s->Wh1, s->Aa, s->Bb, s->thp0, s->thp1, s->chp0, s->chp1, s->chp2 };
    k_w1<<<256, 256>>>(p1);

    W2P p2 = { s->Aa, s->Bb, s->wc,
               s->thp0, s->thp1, te_b1, te_w2, te_b2,
               s->chp0, s->chp1, s->chp2, co_b1, co_w2, co_b2,
               s->Wh1, a_std1,
               s->Sp0, s->Sp1, s->tf, s->cf4, s->E, s->U };
    k_w2<<<208, 256>>>(p2);

    W3P p3 = { s->Aa, s->Bb, s->Sp0, s->Sp1,
               s->adjf, s->U, s->E, s->tf, s->cf4,
               s->mb, s->seb, s->gpart, s->Np0, s->Np1, s->Np2, s->Np3,
               s->D, s->H3, s->h4 };
    k_w3<<<323, 256>>>(p3);

    k_h2c<<<1, 256>>>(s->mb, s->seb, s->gpart, ce_w2, ce_b2, s->H2);

    W5P p5 = { s->Np0, s->Np1, s->Np2, s->Np3, s->D, s->H2, s->H3, s->h4, W2,
               s->Hcp0, s->Hcp1 };
    k_w5<<<64, 256>>>(p5);

    k_w6<<<32, 256>>>(s->Hcp0, s->Hcp1, Wo, bo, s->op);
    k_lnelu<<<NV, 256>>>(s->op, ln_g, ln_b, out);
}